// round 14
// baseline (speedup 1.0000x reference)
#include <cuda_runtime.h>
#include <math.h>
#include <stdint.h>

// Problem constants
#define BSZ 256     // batch
#define TT  512     // time steps
#define EE  256     // embedding dim
#define HH  256     // hidden dim
#define KH  512     // E + H
#define G3  768     // 3 * H (z, r, m)
#define MTOT (BSZ * TT)   // 131072 GEMM rows, m = t*256 + b

typedef unsigned long long u64;

// Scratch (device globals: allocation-free rule)
__device__ float   g_bias[G3];
__device__ float   g_WT[EE * G3];               // x-GEMM weights: WT[k][g*H+j]
__device__ float2  g_Wzr[HH * HH];              // recurrent z/r interleaved [k][j]
__device__ float   g_Wm2[HH * HH];              // recurrent m [k][j]
__device__ float   g_Gx[(size_t)MTOT * G3];     // x-part + bias, layout [t][b][3H]

// ---------------------------------------------------------------------------
// PTX helpers
// ---------------------------------------------------------------------------
__device__ __forceinline__ u64 pack2(float lo, float hi) {
    u64 r; asm("mov.b64 %0, {%1, %2};" : "=l"(r) : "f"(lo), "f"(hi)); return r;
}
__device__ __forceinline__ float2 unpack2(u64 v) {
    float2 r; asm("mov.b64 {%0, %1}, %2;" : "=f"(r.x), "=f"(r.y) : "l"(v)); return r;
}
__device__ __forceinline__ void ffma2(u64& d, u64 a, u64 b) {
    asm("fma.rn.f32x2 %0, %1, %2, %0;" : "+l"(d) : "l"(a), "l"(b));
}
__device__ __forceinline__ u64 add2(u64 a, u64 b) {
    u64 r; asm("add.rn.f32x2 %0, %1, %2;" : "=l"(r) : "l"(a), "l"(b)); return r;
}
__device__ __forceinline__ uint32_t smem_u32(const void* p) {
    uint32_t a;
    asm("{ .reg .u64 t; cvta.to.shared.u64 t, %1; cvt.u32.u64 %0, t; }" : "=r"(a) : "l"(p));
    return a;
}
__device__ __forceinline__ uint32_t mapa_u32(uint32_t a, uint32_t rank) {
    uint32_t r; asm("mapa.shared::cluster.u32 %0, %1, %2;" : "=r"(r) : "r"(a), "r"(rank)); return r;
}
// async store to (possibly remote) cluster smem; increments dest CTA's mbarrier
// tx-count by 8 bytes on completion (data-visible before tx signal).
__device__ __forceinline__ void st_async_b64(uint32_t raddr, u64 v, uint32_t rmbar) {
    asm volatile(
        "st.async.weak.shared::cluster.mbarrier::complete_tx::bytes.b64 [%0], %1, [%2];"
        :: "r"(raddr), "l"(v), "r"(rmbar) : "memory");
}
#define MBAR_INIT(mbar, cnt) \
    asm volatile("mbarrier.init.shared.b64 [%0], %1;" :: "r"((uint32_t)(mbar)), "r"((uint32_t)(cnt)) : "memory")
#define MBAR_EXPECT_TX(mbar, bytes) \
    asm volatile("mbarrier.arrive.expect_tx.shared.b64 _, [%0], %1;" \
                 :: "r"((uint32_t)(mbar)), "r"((uint32_t)(bytes)) : "memory")

__device__ __forceinline__ void mbar_wait(uint32_t mbar, uint32_t parity) {
    uint32_t done;
    asm volatile(
        "{\n\t.reg .pred p;\n\t"
        "mbarrier.try_wait.parity.acquire.cta.shared::cta.b64 p, [%1], %2;\n\t"
        "selp.b32 %0, 1, 0, p;\n\t}"
        : "=r"(done) : "r"(mbar), "r"(parity) : "memory");
    if (!done) {
        asm volatile(
            "{\n\t.reg .pred P1;\n\t"
            "WL_%=:\n\t"
            "mbarrier.try_wait.parity.acquire.cta.shared::cta.b64 P1, [%0], %1, 0x989680;\n\t"
            "@P1 bra.uni WD_%=;\n\t"
            "bra.uni WL_%=;\n\t"
            "WD_%=:\n\t}"
            :: "r"(mbar), "r"(parity) : "memory");
    }
}
#define CLUSTER_SYNC() do { \
    asm volatile("barrier.cluster.arrive.aligned;" ::: "memory"); \
    asm volatile("barrier.cluster.wait.aligned;"   ::: "memory"); \
} while (0)

__device__ __forceinline__ float fast_sigmoid(float x) {
    float e = __expf(-x);
    return __fdividef(1.f, 1.f + e);
}
__device__ __forceinline__ float fast_tanh(float x) {
    float e = __expf(2.f * x);
    return __fdividef(e - 1.f, e + 1.f);
}

// ---------------------------------------------------------------------------
// Kernel 1: weight transpose (fp32) + bias + recurrent repack
// ---------------------------------------------------------------------------
__global__ void prep_kernel(const float* __restrict__ Wz, const float* __restrict__ bz,
                            const float* __restrict__ Wr, const float* __restrict__ br,
                            const float* __restrict__ Wm, const float* __restrict__ bm) {
    int idx = blockIdx.x * blockDim.x + threadIdx.x;
    if (idx < EE * G3) {                 // GEMM weights: WT[k][g*256+j] = Wg[j][k], k < EE
        int k  = idx / G3;
        int gj = idx - k * G3;
        int g  = gj >> 8;
        int jj = gj & 255;
        const float* W = (g == 0) ? Wz : (g == 1) ? Wr : Wm;
        g_WT[idx] = W[jj * KH + k];
    }
    if (idx < HH * HH) {                 // recurrent repack (k, j)
        int k = idx >> 8;
        int j = idx & 255;
        g_Wzr[idx] = make_float2(Wz[j * KH + EE + k], Wr[j * KH + EE + k]);
        g_Wm2[idx] = Wm[j * KH + EE + k];
    }
    if (idx < G3) {
        int g  = idx >> 8;
        int jj = idx & 255;
        const float* bb = (g == 0) ? bz : (g == 1) ? br : bm;
        g_bias[idx] = bb[jj];
    }
}

// ---------------------------------------------------------------------------
// Kernel 2: fp32 GEMM with f32x2 packed FMA.
// Gx[m][n] = emb_row(m) . WT[:,n] + bias[n];  M = 131072 (m = t*256+b),
// N = 768, K = 256. Tiles 128x128xBK8, 256 thr, per-thread 8M x 8N with
// M-paired u64 accumulators (A pairs load as u64 straight from smem).
// Legacy mma.sync on sm_103 ≈ same TF/s as f32x2 pipe, so fp32 SIMT wins
// (1 term, full precision) over fp16 2-term.
// ---------------------------------------------------------------------------
#define BM 128
#define BN 128
#define BK 8

__global__ void __launch_bounds__(256, 2) gemm_f32x2_kernel(const float* __restrict__ emb) {
    __shared__ float As[BK][BM];
    __shared__ float Bs[BK][BN];

    int tid = threadIdx.x;
    int m0 = blockIdx.y * BM;
    int n0 = blockIdx.x * BN;

    int tx = tid & 15;        // N microtile (8 floats)
    int ty = tid >> 4;        // M microtile (8 floats = 4 u64 pairs)

    // A tile load mapping: 128 rows x 8 k, one float4 per thread
    int arow = tid >> 1;
    int akq  = (tid & 1) << 2;
    int m    = m0 + arow;
    int bidx = m & (BSZ - 1);          // m = t*256 + b
    int tidx = m >> 8;
    const float* aptr = emb + ((size_t)bidx * TT + tidx) * EE + akq;

    // B tile load mapping: 8 rows x 128 n, one float4 per thread
    int bkr = tid >> 5;
    int bnq = (tid & 31) << 2;
    const float* bptr = g_WT + (size_t)bkr * G3 + n0 + bnq;

    u64 acc[4][8];
#pragma unroll
    for (int q = 0; q < 4; q++)
#pragma unroll
        for (int n = 0; n < 8; n++) acc[q][n] = 0;

    float4 av = *(const float4*)(aptr);
    float4 bv = *(const float4*)(bptr);

    for (int k0 = 0; k0 < EE; k0 += BK) {
        As[akq + 0][arow] = av.x;
        As[akq + 1][arow] = av.y;
        As[akq + 2][arow] = av.z;
        As[akq + 3][arow] = av.w;
        *(float4*)(&Bs[bkr][bnq]) = bv;
        __syncthreads();

        if (k0 + BK < EE) {            // prefetch next global chunk over compute
            av = *(const float4*)(aptr + k0 + BK);
            bv = *(const float4*)(bptr + (size_t)(k0 + BK) * G3);
        }

#pragma unroll
        for (int kk = 0; kk < BK; kk++) {
            u64 ap[4];
            const u64* arow64 = (const u64*)(&As[kk][0]);
            *(ulonglong2*)(ap)     = *(const ulonglong2*)(arow64 + ty * 4);
            *(ulonglong2*)(ap + 2) = *(const ulonglong2*)(arow64 + ty * 4 + 2);
            float b[8];
            *(float4*)(b)     = *(const float4*)(&Bs[kk][tx * 8]);
            *(float4*)(b + 4) = *(const float4*)(&Bs[kk][tx * 8 + 4]);
            u64 bb[8];
#pragma unroll
            for (int n = 0; n < 8; n++) bb[n] = pack2(b[n], b[n]);
#pragma unroll
            for (int q = 0; q < 4; q++)
#pragma unroll
                for (int n = 0; n < 8; n++)
                    ffma2(acc[q][n], ap[q], bb[n]);
        }
        __syncthreads();
    }

    float biasv[8];
    *(float4*)(biasv)     = *(const float4*)(&g_bias[n0 + tx * 8]);
    *(float4*)(biasv + 4) = *(const float4*)(&g_bias[n0 + tx * 8 + 4]);

#pragma unroll
    for (int q = 0; q < 4; q++) {
        int r0 = m0 + ty * 8 + 2 * q;          // acc[q][n].x -> row r0, .y -> row r0+1
        float v0[8], v1[8];
#pragma unroll
        for (int n = 0; n < 8; n++) {
            float2 v = unpack2(acc[q][n]);
            v0[n] = v.x + biasv[n];
            v1[n] = v.y + biasv[n];
        }
        float* gp0 = g_Gx + (size_t)r0 * G3 + n0 + tx * 8;
        float* gp1 = gp0 + G3;
        *(float4*)(gp0)     = *(float4*)(v0);
        *(float4*)(gp0 + 4) = *(float4*)(v0 + 4);
        *(float4*)(gp1)     = *(float4*)(v1);
        *(float4*)(gp1 + 4) = *(float4*)(v1 + 4);
    }
}

// ---------------------------------------------------------------------------
// Kernel 3: recurrent, cluster-of-4, st.async protocol (EXACT R11 version)
// ---------------------------------------------------------------------------
#define SM_WZR 0
#define SM_WM  131072
#define SM_H   196608
#define SM_RH  204800
#define SM_P   212992
#define SM_BAR 231424              // 2 mbarriers (16B)
#define SM_TOTAL 231456

__global__ void __launch_bounds__(256, 1) __cluster_dims__(4, 1, 1)
gru_rec_kernel(float* __restrict__ out) {
    extern __shared__ char smem_raw[];
    float2* wzr_s = (float2*)(smem_raw + SM_WZR);
    float*  wm_s  = (float*)(smem_raw + SM_WM);
    float*  h_s   = (float*)(smem_raw + SM_H);
    float*  rh_s  = (float*)(smem_raw + SM_RH);
    u64*    p_s   = (u64*)(smem_raw + SM_P);

    int tid   = threadIdx.x;
    int jl    = tid & 63;
    int ksub  = tid >> 6;
    int crank = blockIdx.x & 3;
    int b0g   = (blockIdx.x >> 2) * 8;
    int jg    = crank * 64 + jl;

    for (int i = tid; i < HH * 64; i += 256) {
        int k  = i >> 6;
        int j2 = (i & 63) + crank * 64;
        wzr_s[i] = g_Wzr[k * HH + j2];
        wm_s[i]  = g_Wm2[k * HH + j2];
    }
    for (int i = tid; i < HH * 8; i += 256) h_s[i] = 0.f;

    uint32_t bar_rh = smem_u32(smem_raw + SM_BAR);
    uint32_t bar_h  = bar_rh + 8;
    if (tid == 0) {
        MBAR_INIT(bar_rh, 1);
        MBAR_INIT(bar_h, 1);
    }
    __syncthreads();
    CLUSTER_SYNC();    // barriers + h_s init visible cluster-wide before any st.async

    uint32_t rh_local = smem_u32(rh_s);
    uint32_t h_local  = smem_u32(h_s);
    uint32_t rh_dst[4], h_dst[4], rbar_rh[4], rbar_h[4];
#pragma unroll
    for (int d = 0; d < 4; d++) {
        rh_dst[d]  = mapa_u32(rh_local, (uint32_t)d);
        h_dst[d]   = mapa_u32(h_local,  (uint32_t)d);
        rbar_rh[d] = mapa_u32(bar_rh,   (uint32_t)d);
        rbar_h[d]  = mapa_u32(bar_h,    (uint32_t)d);
    }
    uint32_t off_pair = (uint32_t)(jg * 8 + 2 * ksub) * 4;

    int k0 = ksub * 64;

    for (int t = 0; t < TT; t++) {
        uint32_t par = (uint32_t)(t & 1);
        if (tid == 0) {
            MBAR_EXPECT_TX(bar_rh, 8192);
            MBAR_EXPECT_TX(bar_h, 8192);
        }

        const float* gxb = g_Gx + ((size_t)t * BSZ + b0g + 2 * ksub) * G3 + jg;
        float gz0 = __ldg(gxb);            float gr0 = __ldg(gxb + HH);
        float gm0 = __ldg(gxb + 2 * HH);
        float gz1 = __ldg(gxb + G3);       float gr1 = __ldg(gxb + G3 + HH);
        float gm1 = __ldg(gxb + G3 + 2 * HH);

        u64 az0 = 0, az1 = 0, az2 = 0, az3 = 0;
        u64 ar0 = 0, ar1 = 0, ar2 = 0, ar3 = 0;
#pragma unroll 4
        for (int kk = 0; kk < 64; kk++) {
            int k = k0 + kk;
            float2 w = wzr_s[k * 64 + jl];
            u64 wzz = pack2(w.x, w.x);
            u64 wrr = pack2(w.y, w.y);
            ulonglong2 ha = *(const ulonglong2*)(h_s + k * 8);
            ulonglong2 hb = *(const ulonglong2*)(h_s + k * 8 + 4);
            ffma2(az0, wzz, ha.x); ffma2(az1, wzz, ha.y);
            ffma2(az2, wzz, hb.x); ffma2(az3, wzz, hb.y);
            ffma2(ar0, wrr, ha.x); ffma2(ar1, wrr, ha.y);
            ffma2(ar2, wrr, hb.x); ffma2(ar3, wrr, hb.y);
        }
        {
            u64* pr = p_s + (ksub * 64 + jl) * 9;
            pr[0] = az0; pr[1] = az1; pr[2] = az2; pr[3] = az3;
            pr[4] = ar0; pr[5] = ar1; pr[6] = ar2; pr[7] = ar3;
        }
        __syncthreads();

        u64 zz = 0, rr = 0;
#pragma unroll
        for (int ks = 0; ks < 4; ks++) {
            const u64* pr = p_s + (ks * 64 + jl) * 9;
            zz = add2(zz, pr[ksub]);
            rr = add2(rr, pr[4 + ksub]);
        }
        float2 zf = unpack2(zz), rf = unpack2(rr);
        float z0 = fast_sigmoid(zf.x + gz0);
        float z1 = fast_sigmoid(zf.y + gz1);
        float r0 = fast_sigmoid(rf.x + gr0);
        float r1 = fast_sigmoid(rf.y + gr1);
        float2 hold = *(const float2*)(h_s + jg * 8 + 2 * ksub);
        u64 rhp = pack2(r0 * hold.x, r1 * hold.y);
#pragma unroll
        for (int d = 0; d < 4; d++)
            st_async_b64(rh_dst[d] + off_pair, rhp, rbar_rh[d]);
        mbar_wait(bar_rh, par);

        u64 am0 = 0, am1 = 0, am2 = 0, am3 = 0;
#pragma unroll 4
        for (int kk = 0; kk < 64; kk++) {
            int k = k0 + kk;
            float wm = wm_s[k * 64 + jl];
            u64 wmm = pack2(wm, wm);
            ulonglong2 ra = *(const ulonglong2*)(rh_s + k * 8);
            ulonglong2 rb = *(const ulonglong2*)(rh_s + k * 8 + 4);
            ffma2(am0, wmm, ra.x); ffma2(am1, wmm, ra.y);
            ffma2(am2, wmm, rb.x); ffma2(am3, wmm, rb.y);
        }
        {
            u64* pr = p_s + (ksub * 64 + jl) * 9;
            pr[0] = am0; pr[1] = am1; pr[2] = am2; pr[3] = am3;
        }
        __syncthreads();

        u64 mm = 0;
#pragma unroll
        for (int ks = 0; ks < 4; ks++)
            mm = add2(mm, p_s[(ks * 64 + jl) * 9 + ksub]);
        float2 mf = unpack2(mm);
        float hc0 = fast_tanh(mf.x + gm0);
        float hc1 = fast_tanh(mf.y + gm1);
        float hn0 = fmaf(z0, hc0 - hold.x, hold.x);
        float hn1 = fmaf(z1, hc1 - hold.y, hold.y);
        u64 hp = pack2(hn0, hn1);
#pragma unroll
        for (int d = 0; d < 4; d++)
            st_async_b64(h_dst[d] + off_pair, hp, rbar_h[d]);

        float* op = out + ((size_t)(b0g + 2 * ksub) * TT + t) * HH + jg;
        op[0]               = hn0;
        op[(size_t)TT * HH] = hn1;
        mbar_wait(bar_h, par);
    }
    CLUSTER_SYNC();    // no CTA exits while peers could still target its smem
}

// ---------------------------------------------------------------------------
// Launch
// ---------------------------------------------------------------------------
extern "C" void kernel_launch(void* const* d_in, const int* in_sizes, int n_in,
                              void* d_out, int out_size) {
    const float* emb = (const float*)d_in[0];
    const float* Wz  = (const float*)d_in[1];
    const float* bz  = (const float*)d_in[2];
    const float* Wr  = (const float*)d_in[3];
    const float* br  = (const float*)d_in[4];
    const float* Wm  = (const float*)d_in[5];
    const float* bm  = (const float*)d_in[6];
    float* out = (float*)d_out;

    cudaFuncSetAttribute(gru_rec_kernel,
                         cudaFuncAttributeMaxDynamicSharedMemorySize, SM_TOTAL);

    prep_kernel<<<(EE * G3 + 255) / 256, 256>>>(Wz, bz, Wr, br, Wm, bm);
    gemm_f32x2_kernel<<<dim3(G3 / BN, MTOT / BM), 256>>>(emb);
    gru_rec_kernel<<<128, 256, SM_TOTAL>>>(out);
}

// round 15
// speedup vs baseline: 1.1850x; 1.1850x over previous
#include <cuda_runtime.h>
#include <cuda_fp16.h>
#include <math.h>
#include <stdint.h>

// Problem constants
#define BSZ 256     // batch
#define TT  512     // time steps
#define EE  256     // embedding dim
#define HH  256     // hidden dim
#define KH  512     // E + H
#define G3  768     // 3 * H (z, r, m)
#define MTOT (BSZ * TT)   // 131072 GEMM rows, m = t*256 + b

typedef unsigned long long u64;

// Scratch (device globals: allocation-free rule)
__device__ float   g_bias[G3];
__device__ float2  g_Wzr[HH * HH];              // recurrent z/r interleaved [k][j]
__device__ float   g_Wm2[HH * HH];              // recurrent m [k][j]
__device__ __half  g_Bh [G3 * EE];              // B row n=g*256+j, col k: fp16 of Wg[j][k]
__device__ __half  g_Ahi[(size_t)MTOT * EE];    // A row m=t*256+b: fp16 hi of emb
__device__ __half  g_Alo[(size_t)MTOT * EE];    // fp16 lo residual
__device__ float   g_Gx[(size_t)MTOT * G3];     // x-part + bias, layout [t][b][3H]

// ---------------------------------------------------------------------------
// PTX helpers
// ---------------------------------------------------------------------------
__device__ __forceinline__ u64 pack2(float lo, float hi) {
    u64 r; asm("mov.b64 %0, {%1, %2};" : "=l"(r) : "f"(lo), "f"(hi)); return r;
}
__device__ __forceinline__ float2 unpack2(u64 v) {
    float2 r; asm("mov.b64 {%0, %1}, %2;" : "=f"(r.x), "=f"(r.y) : "l"(v)); return r;
}
__device__ __forceinline__ void ffma2(u64& d, u64 a, u64 b) {
    asm("fma.rn.f32x2 %0, %1, %2, %0;" : "+l"(d) : "l"(a), "l"(b));
}
__device__ __forceinline__ u64 add2(u64 a, u64 b) {
    u64 r; asm("add.rn.f32x2 %0, %1, %2;" : "=l"(r) : "l"(a), "l"(b)); return r;
}
__device__ __forceinline__ uint32_t smem_u32(const void* p) {
    uint32_t a;
    asm("{ .reg .u64 t; cvta.to.shared.u64 t, %1; cvt.u32.u64 %0, t; }" : "=r"(a) : "l"(p));
    return a;
}
__device__ __forceinline__ uint32_t mapa_u32(uint32_t a, uint32_t rank) {
    uint32_t r; asm("mapa.shared::cluster.u32 %0, %1, %2;" : "=r"(r) : "r"(a), "r"(rank)); return r;
}
// async store to (possibly remote) cluster smem; increments dest CTA's mbarrier
// tx-count by 8 bytes on completion (data-visible before tx signal).
__device__ __forceinline__ void st_async_b64(uint32_t raddr, u64 v, uint32_t rmbar) {
    asm volatile(
        "st.async.weak.shared::cluster.mbarrier::complete_tx::bytes.b64 [%0], %1, [%2];"
        :: "r"(raddr), "l"(v), "r"(rmbar) : "memory");
}
#define MBAR_INIT(mbar, cnt) \
    asm volatile("mbarrier.init.shared.b64 [%0], %1;" :: "r"((uint32_t)(mbar)), "r"((uint32_t)(cnt)) : "memory")
#define MBAR_EXPECT_TX(mbar, bytes) \
    asm volatile("mbarrier.arrive.expect_tx.shared.b64 _, [%0], %1;" \
                 :: "r"((uint32_t)(mbar)), "r"((uint32_t)(bytes)) : "memory")

__device__ __forceinline__ void mbar_wait(uint32_t mbar, uint32_t parity) {
    uint32_t done;
    asm volatile(
        "{\n\t.reg .pred p;\n\t"
        "mbarrier.try_wait.parity.acquire.cta.shared::cta.b64 p, [%1], %2;\n\t"
        "selp.b32 %0, 1, 0, p;\n\t}"
        : "=r"(done) : "r"(mbar), "r"(parity) : "memory");
    if (!done) {
        asm volatile(
            "{\n\t.reg .pred P1;\n\t"
            "WL_%=:\n\t"
            "mbarrier.try_wait.parity.acquire.cta.shared::cta.b64 P1, [%0], %1, 0x989680;\n\t"
            "@P1 bra.uni WD_%=;\n\t"
            "bra.uni WL_%=;\n\t"
            "WD_%=:\n\t}"
            :: "r"(mbar), "r"(parity) : "memory");
    }
}
#define CLUSTER_SYNC() do { \
    asm volatile("barrier.cluster.arrive.aligned;" ::: "memory"); \
    asm volatile("barrier.cluster.wait.aligned;"   ::: "memory"); \
} while (0)

__device__ __forceinline__ float fast_sigmoid(float x) {
    float e = __expf(-x);
    return __fdividef(1.f, 1.f + e);
}
__device__ __forceinline__ float fast_tanh(float x) {
    float e = __expf(2.f * x);
    return __fdividef(e - 1.f, e + 1.f);
}

// ---- warp-level MMA helpers (fp16 inputs, fp32 accum) ----
__device__ __forceinline__ void ldsm_x4(uint32_t* r, uint32_t addr) {
    asm volatile("ldmatrix.sync.aligned.m8n8.x4.shared.b16 {%0,%1,%2,%3}, [%4];"
        : "=r"(r[0]), "=r"(r[1]), "=r"(r[2]), "=r"(r[3]) : "r"(addr));
}
__device__ __forceinline__ void ldsm_x2(uint32_t* r, uint32_t addr) {
    asm volatile("ldmatrix.sync.aligned.m8n8.x2.shared.b16 {%0,%1}, [%2];"
        : "=r"(r[0]), "=r"(r[1]) : "r"(addr));
}
__device__ __forceinline__ void mma16816(float* d, const uint32_t* a, const uint32_t* b) {
    asm volatile(
        "mma.sync.aligned.m16n8k16.row.col.f32.f16.f16.f32 "
        "{%0,%1,%2,%3}, {%4,%5,%6,%7}, {%8,%9}, {%0,%1,%2,%3};"
        : "+f"(d[0]), "+f"(d[1]), "+f"(d[2]), "+f"(d[3])
        : "r"(a[0]), "r"(a[1]), "r"(a[2]), "r"(a[3]), "r"(b[0]), "r"(b[1]));
}

// ---------------------------------------------------------------------------
// Kernel 1: bias + recurrent repack + B fp16 convert (R11 exact)
// ---------------------------------------------------------------------------
__global__ void prep_kernel(const float* __restrict__ Wz, const float* __restrict__ bz,
                            const float* __restrict__ Wr, const float* __restrict__ br,
                            const float* __restrict__ Wm, const float* __restrict__ bm) {
    int idx = blockIdx.x * blockDim.x + threadIdx.x;
    if (idx < G3 * EE) {                 // B: row n = g*256+j, col k
        int n = idx >> 8;
        int k = idx & 255;
        int g = n >> 8;
        int j = n & 255;
        const float* W = (g == 0) ? Wz : (g == 1) ? Wr : Wm;
        g_Bh[idx] = __float2half_rn(W[j * KH + k]);
    }
    if (idx < HH * HH) {                 // recurrent repack (k, j)
        int k = idx >> 8;
        int j = idx & 255;
        g_Wzr[idx] = make_float2(Wz[j * KH + EE + k], Wr[j * KH + EE + k]);
        g_Wm2[idx] = Wm[j * KH + EE + k];
    }
    if (idx < G3) {
        int g  = idx >> 8;
        int jj = idx & 255;
        const float* bb = (g == 0) ? bz : (g == 1) ? br : bm;
        g_bias[idx] = bb[jj];
    }
}

// ---------------------------------------------------------------------------
// Kernel 1b: A hi/lo fp16 split (R11 exact)
// ---------------------------------------------------------------------------
__global__ __launch_bounds__(256) void conv_a_kernel(const float* __restrict__ emb) {
    size_t q = (size_t)blockIdx.x * 256 + threadIdx.x;   // quad index
    size_t m = q >> 6;
    int kq = (int)(q & 63) * 4;
    int b = (int)(m & 255);
    int t = (int)(m >> 8);
    float4 v = *(const float4*)(emb + ((size_t)b * TT + t) * EE + kq);
    __half h0 = __float2half_rn(v.x), h1 = __float2half_rn(v.y);
    __half h2 = __float2half_rn(v.z), h3 = __float2half_rn(v.w);
    __half hv[4] = {h0, h1, h2, h3};
    __half lv[4] = {
        __float2half_rn(v.x - __half2float(h0)),
        __float2half_rn(v.y - __half2float(h1)),
        __float2half_rn(v.z - __half2float(h2)),
        __float2half_rn(v.w - __half2float(h3))};
    *(uint2*)(g_Ahi + m * EE + kq) = *(const uint2*)hv;
    *(uint2*)(g_Alo + m * EE + kq) = *(const uint2*)lv;
}

// ---------------------------------------------------------------------------
// Kernel 2: 2-term fp16 GEMM via mma.sync. SINGLE CHANGE vs R11:
// split-k accumulators — even/odd k16 rounds feed independent acc sets,
// doubling per-warp HMMA chains (8 -> 16) and halving chain length, to
// attack the suspected mma-latency bound. Summed in epilogue.
// ---------------------------------------------------------------------------
#define LDA 264                          // A smem row stride (halves)
#define LDB 136                          // B smem row stride (halves)
#define SA_HI 0
#define SA_LO (128 * LDA * 2)            //  67584
#define SB    (2 * 128 * LDA * 2)        // 135168
#define GEMM_SMEM (SB + 128 * LDB * 2)   // 169984

__global__ void __launch_bounds__(512, 1) gemm_mma_kernel() {
    extern __shared__ char smem[];
    uint32_t sbase = smem_u32(smem);
    int tid  = threadIdx.x;
    int warp = tid >> 5;
    int lane = tid & 31;
    int m0 = blockIdx.x * 128;

    int wm = (warp >> 2) * 32;           // warp M offset
    int wn = (warp & 3) * 32;            // warp N offset

    for (int u = tid; u < 128 * 32; u += 512) {
        int row = u >> 5;
        int c   = u & 31;
        size_t src = (size_t)(m0 + row) * EE + c * 8;
        int dst = (row * LDA + c * 8) * 2;
        *(uint4*)(smem + SA_HI + dst) = *(const uint4*)(g_Ahi + src);
        *(uint4*)(smem + SA_LO + dst) = *(const uint4*)(g_Alo + src);
    }

    uint32_t a_row  = (uint32_t)(wm + (lane & 15));
    uint32_t a_coff = (uint32_t)((lane >> 4) * 8);
    uint32_t b_row  = (uint32_t)(wn + (lane & 7));
    uint32_t b_coff = (uint32_t)(((lane >> 3) & 1) * 8);

    for (int nj = 0; nj < 6; nj++) {
        float acc[2][2][4][4];           // [k16 parity][mi][ni][q]
#pragma unroll
        for (int p = 0; p < 2; p++)
#pragma unroll
            for (int mi = 0; mi < 2; mi++)
#pragma unroll
                for (int ni = 0; ni < 4; ni++)
#pragma unroll
                    for (int q = 0; q < 4; q++) acc[p][mi][ni][q] = 0.f;

        for (int kt = 0; kt < 2; kt++) {
            __syncthreads();
            for (int u = tid; u < 128 * 16; u += 512) {
                int row = u >> 4;
                int c   = u & 15;
                size_t src = (size_t)(nj * 128 + row) * EE + kt * 128 + c * 8;
                int dst = (row * LDB + c * 8) * 2;
                *(uint4*)(smem + SB + dst) = *(const uint4*)(g_Bh + src);
            }
            __syncthreads();

#pragma unroll
            for (int k16 = 0; k16 < 8; k16++) {
                int par = k16 & 1;
                int kA = kt * 128 + k16 * 16;
                int kB = k16 * 16;

                uint32_t aH[2][4], aL[2][4];
#pragma unroll
                for (int mi = 0; mi < 2; mi++) {
                    uint32_t off = ((a_row + mi * 16) * LDA + kA + a_coff) * 2;
                    ldsm_x4(aH[mi], sbase + SA_HI + off);
                    ldsm_x4(aL[mi], sbase + SA_LO + off);
                }
                uint32_t bF[4][2];
#pragma unroll
                for (int ni = 0; ni < 4; ni++) {
                    uint32_t off = ((b_row + ni * 8) * LDB + kB + b_coff) * 2;
                    ldsm_x2(bF[ni], sbase + SB + off);
                }
#pragma unroll
                for (int mi = 0; mi < 2; mi++)
#pragma unroll
                    for (int ni = 0; ni < 4; ni++)
                        mma16816(acc[par][mi][ni], aH[mi], bF[ni]);
#pragma unroll
                for (int mi = 0; mi < 2; mi++)
#pragma unroll
                    for (int ni = 0; ni < 4; ni++)
                        mma16816(acc[par][mi][ni], aL[mi], bF[ni]);
            }
        }

        int row0 = m0 + wm + (lane >> 2);
#pragma unroll
        for (int mi = 0; mi < 2; mi++) {
#pragma unroll
            for (int ni = 0; ni < 4; ni++) {
                int n = nj * 128 + wn + ni * 8 + 2 * (lane & 3);
                float bb0 = __ldg(g_bias + n);
                float bb1 = __ldg(g_bias + n + 1);
                float2 v0 = make_float2(
                    acc[0][mi][ni][0] + acc[1][mi][ni][0] + bb0,
                    acc[0][mi][ni][1] + acc[1][mi][ni][1] + bb1);
                float2 v1 = make_float2(
                    acc[0][mi][ni][2] + acc[1][mi][ni][2] + bb0,
                    acc[0][mi][ni][3] + acc[1][mi][ni][3] + bb1);
                *(float2*)(g_Gx + (size_t)(row0 + mi * 16) * G3 + n)     = v0;
                *(float2*)(g_Gx + (size_t)(row0 + mi * 16 + 8) * G3 + n) = v1;
            }
        }
    }
}

// ---------------------------------------------------------------------------
// Kernel 3: recurrent, cluster-of-4, st.async protocol (EXACT R11 version)
// ---------------------------------------------------------------------------
#define SM_WZR 0
#define SM_WM  131072
#define SM_H   196608
#define SM_RH  204800
#define SM_P   212992
#define SM_BAR 231424              // 2 mbarriers (16B)
#define SM_TOTAL 231456

__global__ void __launch_bounds__(256, 1) __cluster_dims__(4, 1, 1)
gru_rec_kernel(float* __restrict__ out) {
    extern __shared__ char smem_raw[];
    float2* wzr_s = (float2*)(smem_raw + SM_WZR);
    float*  wm_s  = (float*)(smem_raw + SM_WM);
    float*  h_s   = (float*)(smem_raw + SM_H);
    float*  rh_s  = (float*)(smem_raw + SM_RH);
    u64*    p_s   = (u64*)(smem_raw + SM_P);

    int tid   = threadIdx.x;
    int jl    = tid & 63;
    int ksub  = tid >> 6;
    int crank = blockIdx.x & 3;
    int b0g   = (blockIdx.x >> 2) * 8;
    int jg    = crank * 64 + jl;

    for (int i = tid; i < HH * 64; i += 256) {
        int k  = i >> 6;
        int j2 = (i & 63) + crank * 64;
        wzr_s[i] = g_Wzr[k * HH + j2];
        wm_s[i]  = g_Wm2[k * HH + j2];
    }
    for (int i = tid; i < HH * 8; i += 256) h_s[i] = 0.f;

    uint32_t bar_rh = smem_u32(smem_raw + SM_BAR);
    uint32_t bar_h  = bar_rh + 8;
    if (tid == 0) {
        MBAR_INIT(bar_rh, 1);
        MBAR_INIT(bar_h, 1);
    }
    __syncthreads();
    CLUSTER_SYNC();    // barriers + h_s init visible cluster-wide before any st.async

    uint32_t rh_local = smem_u32(rh_s);
    uint32_t h_local  = smem_u32(h_s);
    uint32_t rh_dst[4], h_dst[4], rbar_rh[4], rbar_h[4];
#pragma unroll
    for (int d = 0; d < 4; d++) {
        rh_dst[d]  = mapa_u32(rh_local, (uint32_t)d);
        h_dst[d]   = mapa_u32(h_local,  (uint32_t)d);
        rbar_rh[d] = mapa_u32(bar_rh,   (uint32_t)d);
        rbar_h[d]  = mapa_u32(bar_h,    (uint32_t)d);
    }
    uint32_t off_pair = (uint32_t)(jg * 8 + 2 * ksub) * 4;

    int k0 = ksub * 64;

    for (int t = 0; t < TT; t++) {
        uint32_t par = (uint32_t)(t & 1);
        if (tid == 0) {
            MBAR_EXPECT_TX(bar_rh, 8192);
            MBAR_EXPECT_TX(bar_h, 8192);
        }

        const float* gxb = g_Gx + ((size_t)t * BSZ + b0g + 2 * ksub) * G3 + jg;
        float gz0 = __ldg(gxb);            float gr0 = __ldg(gxb + HH);
        float gm0 = __ldg(gxb + 2 * HH);
        float gz1 = __ldg(gxb + G3);       float gr1 = __ldg(gxb + G3 + HH);
        float gm1 = __ldg(gxb + G3 + 2 * HH);

        u64 az0 = 0, az1 = 0, az2 = 0, az3 = 0;
        u64 ar0 = 0, ar1 = 0, ar2 = 0, ar3 = 0;
#pragma unroll 4
        for (int kk = 0; kk < 64; kk++) {
            int k = k0 + kk;
            float2 w = wzr_s[k * 64 + jl];
            u64 wzz = pack2(w.x, w.x);
            u64 wrr = pack2(w.y, w.y);
            ulonglong2 ha = *(const ulonglong2*)(h_s + k * 8);
            ulonglong2 hb = *(const ulonglong2*)(h_s + k * 8 + 4);
            ffma2(az0, wzz, ha.x); ffma2(az1, wzz, ha.y);
            ffma2(az2, wzz, hb.x); ffma2(az3, wzz, hb.y);
            ffma2(ar0, wrr, ha.x); ffma2(ar1, wrr, ha.y);
            ffma2(ar2, wrr, hb.x); ffma2(ar3, wrr, hb.y);
        }
        {
            u64* pr = p_s + (ksub * 64 + jl) * 9;
            pr[0] = az0; pr[1] = az1; pr[2] = az2; pr[3] = az3;
            pr[4] = ar0; pr[5] = ar1; pr[6] = ar2; pr[7] = ar3;
        }
        __syncthreads();

        u64 zz = 0, rr = 0;
#pragma unroll
        for (int ks = 0; ks < 4; ks++) {
            const u64* pr = p_s + (ks * 64 + jl) * 9;
            zz = add2(zz, pr[ksub]);
            rr = add2(rr, pr[4 + ksub]);
        }
        float2 zf = unpack2(zz), rf = unpack2(rr);
        float z0 = fast_sigmoid(zf.x + gz0);
        float z1 = fast_sigmoid(zf.y + gz1);
        float r0 = fast_sigmoid(rf.x + gr0);
        float r1 = fast_sigmoid(rf.y + gr1);
        float2 hold = *(const float2*)(h_s + jg * 8 + 2 * ksub);
        u64 rhp = pack2(r0 * hold.x, r1 * hold.y);
#pragma unroll
        for (int d = 0; d < 4; d++)
            st_async_b64(rh_dst[d] + off_pair, rhp, rbar_rh[d]);
        mbar_wait(bar_rh, par);

        u64 am0 = 0, am1 = 0, am2 = 0, am3 = 0;
#pragma unroll 4
        for (int kk = 0; kk < 64; kk++) {
            int k = k0 + kk;
            float wm = wm_s[k * 64 + jl];
            u64 wmm = pack2(wm, wm);
            ulonglong2 ra = *(const ulonglong2*)(rh_s + k * 8);
            ulonglong2 rb = *(const ulonglong2*)(rh_s + k * 8 + 4);
            ffma2(am0, wmm, ra.x); ffma2(am1, wmm, ra.y);
            ffma2(am2, wmm, rb.x); ffma2(am3, wmm, rb.y);
        }
        {
            u64* pr = p_s + (ksub * 64 + jl) * 9;
            pr[0] = am0; pr[1] = am1; pr[2] = am2; pr[3] = am3;
        }
        __syncthreads();

        u64 mm = 0;
#pragma unroll
        for (int ks = 0; ks < 4; ks++)
            mm = add2(mm, p_s[(ks * 64 + jl) * 9 + ksub]);
        float2 mf = unpack2(mm);
        float hc0 = fast_tanh(mf.x + gm0);
        float hc1 = fast_tanh(mf.y + gm1);
        float hn0 = fmaf(z0, hc0 - hold.x, hold.x);
        float hn1 = fmaf(z1, hc1 - hold.y, hold.y);
        u64 hp = pack2(hn0, hn1);
#pragma unroll
        for (int d = 0; d < 4; d++)
            st_async_b64(h_dst[d] + off_pair, hp, rbar_h[d]);

        float* op = out + ((size_t)(b0g + 2 * ksub) * TT + t) * HH + jg;
        op[0]               = hn0;
        op[(size_t)TT * HH] = hn1;
        mbar_wait(bar_h, par);
    }
    CLUSTER_SYNC();    // no CTA exits while peers could still target its smem
}

// ---------------------------------------------------------------------------
// Launch
// ---------------------------------------------------------------------------
extern "C" void kernel_launch(void* const* d_in, const int* in_sizes, int n_in,
                              void* d_out, int out_size) {
    const float* emb = (const float*)d_in[0];
    const float* Wz  = (const float*)d_in[1];
    const float* bz  = (const float*)d_in[2];
    const float* Wr  = (const float*)d_in[3];
    const float* br  = (const float*)d_in[4];
    const float* Wm  = (const float*)d_in[5];
    const float* bm  = (const float*)d_in[6];
    float* out = (float*)d_out;

    cudaFuncSetAttribute(gemm_mma_kernel,
                         cudaFuncAttributeMaxDynamicSharedMemorySize, GEMM_SMEM);
    cudaFuncSetAttribute(gru_rec_kernel,
                         cudaFuncAttributeMaxDynamicSharedMemorySize, SM_TOTAL);

    prep_kernel<<<(G3 * EE + 255) / 256, 256>>>(Wz, bz, Wr, br, Wm, bm);
    conv_a_kernel<<<(int)(((size_t)MTOT * EE / 4) / 256), 256>>>(emb);
    gemm_mma_kernel<<<MTOT / 128, 512, GEMM_SMEM>>>();
    gru_rec_kernel<<<128, 256, SM_TOTAL>>>(out);
}